// round 1
// baseline (speedup 1.0000x reference)
#include <cuda_runtime.h>
#include <math.h>

#define BB 8
#define LL 2048
#define DIM 1024
#define ACT 256
#define HID 256
#define TOK (BB*LL)
#define EPSV 1e-6f
#define KSZ 5
#define NCHUNK 32
#define CHLEN 64

// ---------------- scratch (device globals; no allocation allowed) ----------------
__device__ float g_xn[TOK*DIM];     // rmsnorm output
__device__ float g_xc[TOK*DIM];     // depthwise conv output
__device__ float g_y [TOK*DIM];     // pw gemm + recurrent concat
__device__ float g_a [TOK*DIM];     // y@W1^T + b1
__device__ float g_b2[TOK*DIM];     // y@W2^T + b2
__device__ float g_y2[TOK*DIM];     // gated
__device__ float g_g [TOK*HID];     // gelu(down)
__device__ float g_h [TOK*ACT];     // recurrence states
__device__ float g_carry[BB*NCHUNK*ACT];
__device__ float g_F    [BB*NCHUNK*ACT];

// ---------------- rmsnorm: one block per token ----------------
__global__ void rmsnorm_k(const float* __restrict__ x, const float* __restrict__ w) {
    int tok = blockIdx.x;
    const float4* xr = (const float4*)(x + (size_t)tok * DIM);
    float4 v = xr[threadIdx.x];
    float ss = v.x*v.x + v.y*v.y + v.z*v.z + v.w*v.w;
    #pragma unroll
    for (int o = 16; o; o >>= 1) ss += __shfl_xor_sync(0xffffffffu, ss, o);
    __shared__ float red[8];
    if ((threadIdx.x & 31) == 0) red[threadIdx.x >> 5] = ss;
    __syncthreads();
    float tot = 0.f;
    #pragma unroll
    for (int i = 0; i < 8; i++) tot += red[i];
    float inv = rsqrtf(tot * (1.0f / DIM) + EPSV);
    const float4* wr = (const float4*)w;
    float4 wv = wr[threadIdx.x];
    float4 o;
    o.x = v.x * inv * wv.x;
    o.y = v.y * inv * wv.y;
    o.z = v.z * inv * wv.z;
    o.w = v.w * inv * wv.w;
    ((float4*)g_xn)[(size_t)tok * (DIM/4) + threadIdx.x] = o;
}

// ---------------- depthwise conv K=5, pad 2, per-batch ----------------
__global__ void conv_k(const float* __restrict__ dw_w, const float* __restrict__ dw_b) {
    int idx = blockIdx.x * blockDim.x + threadIdx.x;   // over TOK*DIM
    int c   = idx & (DIM - 1);
    int tok = idx >> 10;
    int t   = tok & (LL - 1);
    float acc = dw_b[c];
    #pragma unroll
    for (int k = 0; k < KSZ; k++) {
        int tt = t + k - 2;
        if (tt >= 0 && tt < LL)
            acc += g_xn[idx + (k - 2) * DIM] * dw_w[c * KSZ + k];
    }
    g_xc[idx] = acc;
}

// ---------------- recurrence: chunked scan ----------------
// local scans (zero init) per (b, chunk), 256 channels per block
__global__ void rec1_k(const float* __restrict__ alpha, const float* __restrict__ beta) {
    int b = blockIdx.x / NCHUNK, j = blockIdx.x % NCHUNK;
    int c = threadIdx.x;
    float al = alpha[c], be = beta[c];
    float h = 0.f;
    int t0 = j * CHLEN;
    const float* src = g_xn + ((size_t)(b * LL + t0)) * DIM + c;
    float*       dst = g_h  + ((size_t)(b * LL + t0)) * ACT + c;
    #pragma unroll 8
    for (int i = 0; i < CHLEN; i++) {
        h = al * h + be * src[(size_t)i * DIM];
        dst[(size_t)i * ACT] = h;
    }
    g_carry[(b * NCHUNK + j) * ACT + c] = h;
}

// propagate chunk carries: g_F[b,j,c] = state entering chunk j
__global__ void rec2_k(const float* __restrict__ alpha) {
    int b = blockIdx.x, c = threadIdx.x;
    float a64 = powf(alpha[c], (float)CHLEN);
    float F = 0.f;
    for (int j = 0; j < NCHUNK; j++) {
        int idx = (b * NCHUNK + j) * ACT + c;
        g_F[idx] = F;
        F = a64 * F + g_carry[idx];
    }
}

// fix-up: h += alpha^(i+1) * incoming_state
__global__ void rec3_k(const float* __restrict__ alpha) {
    int b = blockIdx.x / NCHUNK, j = blockIdx.x % NCHUNK;
    if (j == 0) return;
    int c = threadIdx.x;
    float inc = g_F[(b * NCHUNK + j) * ACT + c];
    float al = alpha[c];
    float m = inc * al;
    float* dst = g_h + ((size_t)(b * LL + j * CHLEN)) * ACT + c;
    #pragma unroll 8
    for (int i = 0; i < CHLEN; i++) {
        dst[(size_t)i * ACT] += m;
        m *= al;
    }
}

// ---------------- generic fp32 tiled GEMM: C[M,N] = A[M,K] @ W[N,K]^T + bias + epilogue ----------------
// EPI 0: + concat(rec h | xn)   (pointwise-conv projection output)
// EPI 1: plain
// EPI 2: gelu (exact erf)
// EPI 3: + add1[m*DIM+n] + add2[m*DIM+n]  (final: + y2 + residual)
template<int EPI>
__global__ __launch_bounds__(256, 2) void gemm_k(
    const float* __restrict__ A, const float* __restrict__ W,
    const float* __restrict__ bias, float* __restrict__ C,
    int N, int K,
    const float* __restrict__ add1, const float* __restrict__ add2)
{
    __shared__ float As[8][128];
    __shared__ float Bs[8][128];
    int bm = blockIdx.y * 128;
    int bn = blockIdx.x * 128;
    int tid = threadIdx.x;
    int tx = tid & 15, ty = tid >> 4;
    int lr = tid >> 1;
    int lk = (tid & 1) * 4;

    const float* Aptr = A + (size_t)(bm + lr) * K + lk;
    const float* Wptr = W + (size_t)(bn + lr) * K + lk;

    float acc[8][8];
    #pragma unroll
    for (int i = 0; i < 8; i++)
        #pragma unroll
        for (int j = 0; j < 8; j++) acc[i][j] = 0.f;

    for (int k0 = 0; k0 < K; k0 += 8) {
        float4 av = *(const float4*)(Aptr + k0);
        float4 wv = *(const float4*)(Wptr + k0);
        As[lk+0][lr] = av.x; As[lk+1][lr] = av.y; As[lk+2][lr] = av.z; As[lk+3][lr] = av.w;
        Bs[lk+0][lr] = wv.x; Bs[lk+1][lr] = wv.y; Bs[lk+2][lr] = wv.z; Bs[lk+3][lr] = wv.w;
        __syncthreads();
        #pragma unroll
        for (int k = 0; k < 8; k++) {
            float4 a0 = *(const float4*)&As[k][ty * 8];
            float4 a1 = *(const float4*)&As[k][ty * 8 + 4];
            float4 b0 = *(const float4*)&Bs[k][tx * 8];
            float4 b1 = *(const float4*)&Bs[k][tx * 8 + 4];
            float ar[8] = {a0.x,a0.y,a0.z,a0.w,a1.x,a1.y,a1.z,a1.w};
            float br[8] = {b0.x,b0.y,b0.z,b0.w,b1.x,b1.y,b1.z,b1.w};
            #pragma unroll
            for (int i = 0; i < 8; i++)
                #pragma unroll
                for (int j = 0; j < 8; j++)
                    acc[i][j] = fmaf(ar[i], br[j], acc[i][j]);
        }
        __syncthreads();
    }

    #pragma unroll
    for (int i = 0; i < 8; i++) {
        int m = bm + ty * 8 + i;
        #pragma unroll
        for (int j = 0; j < 8; j++) {
            int n = bn + tx * 8 + j;
            float v = acc[i][j] + bias[n];
            if (EPI == 0) {
                v += (n < ACT) ? g_h[(size_t)m * ACT + n]
                               : g_xn[(size_t)m * DIM + n];
            } else if (EPI == 2) {
                v = 0.5f * v * (1.f + erff(v * 0.70710678118654752f));
            } else if (EPI == 3) {
                v += add1[(size_t)m * DIM + n] + add2[(size_t)m * DIM + n];
            }
            C[(size_t)m * N + n] = v;
        }
    }
}

// ---------------- gate elementwise: y2 = y + sigmoid(a) * tanh(b) ----------------
__global__ void gate_k() {
    int idx = blockIdx.x * blockDim.x + threadIdx.x;
    float y = g_y[idx];
    float a = g_a[idx];
    float b = g_b2[idx];
    float s = 1.f / (1.f + expf(-a));
    g_y2[idx] = y + s * tanhf(b);
}

// ---------------- launch ----------------
extern "C" void kernel_launch(void* const* d_in, const int* in_sizes, int n_in,
                              void* d_out, int out_size) {
    const float* x      = (const float*)d_in[0];
    const float* norm_w = (const float*)d_in[1];
    const float* dw_w   = (const float*)d_in[2];
    const float* dw_b   = (const float*)d_in[3];
    const float* pw_w   = (const float*)d_in[4];
    const float* pw_b   = (const float*)d_in[5];
    const float* alpha  = (const float*)d_in[6];
    const float* beta   = (const float*)d_in[7];
    const float* W1_w   = (const float*)d_in[8];
    const float* W1_b   = (const float*)d_in[9];
    const float* W2_w   = (const float*)d_in[10];
    const float* W2_b   = (const float*)d_in[11];
    const float* down_w = (const float*)d_in[12];
    const float* down_b = (const float*)d_in[13];
    const float* up_w   = (const float*)d_in[14];
    const float* up_b   = (const float*)d_in[15];
    float* out = (float*)d_out;

    float *p_xn, *p_xc, *p_y, *p_a, *p_b2, *p_y2, *p_g;
    cudaGetSymbolAddress((void**)&p_xn, g_xn);
    cudaGetSymbolAddress((void**)&p_xc, g_xc);
    cudaGetSymbolAddress((void**)&p_y,  g_y);
    cudaGetSymbolAddress((void**)&p_a,  g_a);
    cudaGetSymbolAddress((void**)&p_b2, g_b2);
    cudaGetSymbolAddress((void**)&p_y2, g_y2);
    cudaGetSymbolAddress((void**)&p_g,  g_g);

    rmsnorm_k<<<TOK, 256>>>(x, norm_w);
    conv_k<<<TOK * DIM / 256, 256>>>(dw_w, dw_b);
    rec1_k<<<BB * NCHUNK, ACT>>>(alpha, beta);
    rec2_k<<<BB, ACT>>>(alpha);
    rec3_k<<<BB * NCHUNK, ACT>>>(alpha);

    dim3 gBig(DIM / 128, TOK / 128);
    dim3 gDown(HID / 128, TOK / 128);

    // y = xc @ pw^T + pw_b + concat(h | xn)
    gemm_k<0><<<gBig, 256>>>(p_xc, pw_w, pw_b, p_y, DIM, DIM, nullptr, nullptr);
    // a = y @ W1^T + b1 ; b = y @ W2^T + b2
    gemm_k<1><<<gBig, 256>>>(p_y, W1_w, W1_b, p_a, DIM, DIM, nullptr, nullptr);
    gemm_k<1><<<gBig, 256>>>(p_y, W2_w, W2_b, p_b2, DIM, DIM, nullptr, nullptr);
    gate_k<<<TOK * DIM / 256, 256>>>();
    // g = gelu(y2 @ down^T + down_b)
    gemm_k<2><<<gDown, 256>>>(p_y2, down_w, down_b, p_g, HID, DIM, nullptr, nullptr);
    // out = g @ up^T + up_b + y2 + residual
    gemm_k<3><<<gBig, 256>>>(p_g, up_w, up_b, out, DIM, HID, p_y2, x);
}

// round 3
// speedup vs baseline: 2.2391x; 2.2391x over previous
#include <cuda_runtime.h>
#include <cuda_bf16.h>
#include <math.h>
#include <stdint.h>

#define BB 8
#define LL 2048
#define DIM 1024
#define ACT 256
#define HID 256
#define TOK (BB*LL)
#define EPSV 1e-6f
#define KSZ 5
#define NCHUNK 32
#define CHLEN 64

// ============ scratch (no allocation allowed) ============
__device__ float g_xn[TOK*DIM];
__device__ float g_a [TOK*DIM];
__device__ float g_b2[TOK*DIM];
__device__ float g_h [TOK*ACT];
__device__ float g_carry[BB*NCHUNK*ACT];
__device__ float g_F    [BB*NCHUNK*ACT];

__device__ __nv_bfloat16 g_xch[TOK*DIM], g_xcl[TOK*DIM];
__device__ __nv_bfloat16 g_yh [TOK*DIM], g_yl [TOK*DIM];
__device__ __nv_bfloat16 g_y2h[TOK*DIM], g_y2l[TOK*DIM];
__device__ __nv_bfloat16 g_gh [TOK*HID], g_gl [TOK*HID];
__device__ __nv_bfloat16 g_pwh[DIM*DIM], g_pwl[DIM*DIM];
__device__ __nv_bfloat16 g_w1h[DIM*DIM], g_w1l[DIM*DIM];
__device__ __nv_bfloat16 g_w2h[DIM*DIM], g_w2l[DIM*DIM];
__device__ __nv_bfloat16 g_dnh[HID*DIM], g_dnl[HID*DIM];
__device__ __nv_bfloat16 g_uph[DIM*HID], g_upl[DIM*HID];

__device__ __forceinline__ void split_bf16(float v, __nv_bfloat16& h, __nv_bfloat16& l) {
    h = __float2bfloat16_rn(v);
    l = __float2bfloat16_rn(v - __bfloat162float(h));
}

__device__ __forceinline__ uint32_t smem_u32(const void* p) {
    uint32_t a;
    asm("{ .reg .u64 t; cvta.to.shared.u64 t, %1; cvt.u32.u64 %0, t; }" : "=r"(a) : "l"(p));
    return a;
}

#define CP_ASYNC16(sa, g) \
    asm volatile("cp.async.cg.shared.global [%0], [%1], 16;" :: "r"(sa), "l"(g))
#define CP_COMMIT() asm volatile("cp.async.commit_group;")
#define CP_WAIT(n)  asm volatile("cp.async.wait_group %0;" :: "n"(n))

#define LDMX4(r0, r1, r2, r3, addr) \
    asm volatile("ldmatrix.sync.aligned.m8n8.x4.shared.b16 {%0,%1,%2,%3}, [%4];" \
        : "=r"(r0), "=r"(r1), "=r"(r2), "=r"(r3) : "r"(addr))

#define MMA_BF16(d, a, b) \
    asm volatile("mma.sync.aligned.m16n8k16.row.col.f32.bf16.bf16.f32 " \
        "{%0,%1,%2,%3}, {%4,%5,%6,%7}, {%8,%9}, {%0,%1,%2,%3};" \
        : "+f"((d)[0]), "+f"((d)[1]), "+f"((d)[2]), "+f"((d)[3]) \
        : "r"((a)[0]), "r"((a)[1]), "r"((a)[2]), "r"((a)[3]), "r"((b)[0]), "r"((b)[1]))

// ============ elementwise ============
__global__ void cvt_w_k(const float* __restrict__ src, __nv_bfloat16* __restrict__ hi,
                        __nv_bfloat16* __restrict__ lo, int n) {
    int i = blockIdx.x * blockDim.x + threadIdx.x;
    if (i < n) split_bf16(src[i], hi[i], lo[i]);
}

__global__ void rmsnorm_k(const float* __restrict__ x, const float* __restrict__ w) {
    int tok = blockIdx.x;
    const float4* xr = (const float4*)(x + (size_t)tok * DIM);
    float4 v = xr[threadIdx.x];
    float ss = v.x*v.x + v.y*v.y + v.z*v.z + v.w*v.w;
    #pragma unroll
    for (int o = 16; o; o >>= 1) ss += __shfl_xor_sync(0xffffffffu, ss, o);
    __shared__ float red[8];
    if ((threadIdx.x & 31) == 0) red[threadIdx.x >> 5] = ss;
    __syncthreads();
    float tot = 0.f;
    #pragma unroll
    for (int i = 0; i < 8; i++) tot += red[i];
    float inv = rsqrtf(tot * (1.0f / DIM) + EPSV);
    float4 wv = ((const float4*)w)[threadIdx.x];
    float4 o;
    o.x = v.x * inv * wv.x; o.y = v.y * inv * wv.y;
    o.z = v.z * inv * wv.z; o.w = v.w * inv * wv.w;
    ((float4*)g_xn)[(size_t)tok * (DIM/4) + threadIdx.x] = o;
}

__global__ void conv_k(const float* __restrict__ dw_w, const float* __restrict__ dw_b) {
    int idx = blockIdx.x * blockDim.x + threadIdx.x;
    int c   = idx & (DIM - 1);
    int tok = idx >> 10;
    int t   = tok & (LL - 1);
    float acc = dw_b[c];
    #pragma unroll
    for (int k = 0; k < KSZ; k++) {
        int tt = t + k - 2;
        if (tt >= 0 && tt < LL)
            acc += g_xn[idx + (k - 2) * DIM] * dw_w[c * KSZ + k];
    }
    split_bf16(acc, g_xch[idx], g_xcl[idx]);
}

__global__ void rec1_k(const float* __restrict__ alpha, const float* __restrict__ beta) {
    int b = blockIdx.x / NCHUNK, j = blockIdx.x % NCHUNK;
    int c = threadIdx.x;
    float al = alpha[c], be = beta[c];
    float h = 0.f;
    int t0 = j * CHLEN;
    const float* src = g_xn + ((size_t)(b * LL + t0)) * DIM + c;
    float*       dst = g_h  + ((size_t)(b * LL + t0)) * ACT + c;
    #pragma unroll 8
    for (int i = 0; i < CHLEN; i++) {
        h = al * h + be * src[(size_t)i * DIM];
        dst[(size_t)i * ACT] = h;
    }
    g_carry[(b * NCHUNK + j) * ACT + c] = h;
}
__global__ void rec2_k(const float* __restrict__ alpha) {
    int b = blockIdx.x, c = threadIdx.x;
    float a64 = powf(alpha[c], (float)CHLEN);
    float F = 0.f;
    for (int j = 0; j < NCHUNK; j++) {
        int idx = (b * NCHUNK + j) * ACT + c;
        g_F[idx] = F;
        F = a64 * F + g_carry[idx];
    }
}
__global__ void rec3_k(const float* __restrict__ alpha) {
    int b = blockIdx.x / NCHUNK, j = blockIdx.x % NCHUNK;
    if (j == 0) return;
    int c = threadIdx.x;
    float inc = g_F[(b * NCHUNK + j) * ACT + c];
    float al = alpha[c];
    float m = inc * al;
    float* dst = g_h + ((size_t)(b * LL + j * CHLEN)) * ACT + c;
    #pragma unroll 8
    for (int i = 0; i < CHLEN; i++) {
        dst[(size_t)i * ACT] += m;
        m *= al;
    }
}

__global__ void gate_k() {
    int idx = blockIdx.x * blockDim.x + threadIdx.x;
    float y = __bfloat162float(g_yh[idx]) + __bfloat162float(g_yl[idx]);
    float a = g_a[idx];
    float b = g_b2[idx];
    float s = 1.f / (1.f + expf(-a));
    float y2 = y + s * tanhf(b);
    split_bf16(y2, g_y2h[idx], g_y2l[idx]);
}

// ============ HMMA GEMM ============
// C[M,N] = (Ah+Al)[M,K] @ (Bh+Bl)[N,K]^T + bias + epilogue (split compensation)
// EPI 0: + concat(g_h | g_xn) -> g_yh/g_yl
// EPI 1: plain -> Cf
// EPI 2: gelu  -> g_gh/g_gl
// EPI 3: + y2(recon) + addx -> Cf
#define BLK_K 32
#define PADK 40                        // bf16 elems per smem row (32 + 8 pad)
#define TILE_B (128 * PADK * 2)        // 10240 bytes per tile
#define BUF_B  (4 * TILE_B)            // Ah,Al,Bh,Bl
#define SMEM_TOTAL (2 * BUF_B)         // double buffered = 81920

__device__ __forceinline__ void ld_tile(uint32_t dst, const __nv_bfloat16* __restrict__ src,
                                        int ldK, int row0, int k0, int tid) {
    #pragma unroll
    for (int i = 0; i < 2; i++) {
        int c = tid + i * 256;
        int r = c >> 2, kc = (c & 3) * 8;
        const __nv_bfloat16* g = src + (size_t)(row0 + r) * ldK + k0 + kc;
        CP_ASYNC16(dst + (r * PADK + kc) * 2, g);
    }
}

template<int EPI>
__global__ __launch_bounds__(256, 1) void hgemm(
    const __nv_bfloat16* __restrict__ Ah, const __nv_bfloat16* __restrict__ Al,
    const __nv_bfloat16* __restrict__ Bh, const __nv_bfloat16* __restrict__ Bl,
    const float* __restrict__ bias, float* __restrict__ Cf,
    int N, int K, const float* __restrict__ addx)
{
    extern __shared__ __align__(128) char smem[];
    uint32_t su = smem_u32(smem);
    int tid = threadIdx.x;
    int wid = tid >> 5, lane = tid & 31;
    int warp_m = wid & 1, warp_n = wid >> 1;     // 2 x 4 warps, warp tile 64x32
    int bm = blockIdx.y * 128, bn = blockIdx.x * 128;
    int NS = K / BLK_K;

    float acc[4][4][4];
    #pragma unroll
    for (int i = 0; i < 4; i++)
        #pragma unroll
        for (int j = 0; j < 4; j++)
            #pragma unroll
            for (int f = 0; f < 4; f++) acc[i][j][f] = 0.f;

    // prefetch stage 0
    {
        uint32_t b0 = su;
        ld_tile(b0,              Ah, K, bm, 0, tid);
        ld_tile(b0 + TILE_B,     Al, K, bm, 0, tid);
        ld_tile(b0 + 2 * TILE_B, Bh, K, bn, 0, tid);
        ld_tile(b0 + 3 * TILE_B, Bl, K, bn, 0, tid);
        CP_COMMIT();
    }

    for (int s = 0; s < NS; s++) {
        if (s + 1 < NS) {
            uint32_t nb = su + ((s + 1) & 1) * BUF_B;
            int k0 = (s + 1) * BLK_K;
            ld_tile(nb,              Ah, K, bm, k0, tid);
            ld_tile(nb + TILE_B,     Al, K, bm, k0, tid);
            ld_tile(nb + 2 * TILE_B, Bh, K, bn, k0, tid);
            ld_tile(nb + 3 * TILE_B, Bl, K, bn, k0, tid);
            CP_COMMIT();
            CP_WAIT(1);
        } else {
            CP_WAIT(0);
        }
        __syncthreads();

        uint32_t base = su + (s & 1) * BUF_B;
        #pragma unroll
        for (int kk = 0; kk < 2; kk++) {
            int k0 = kk * 16;
            // A fragments: lanes 0-15 -> rows, lanes 16-31 -> cols+8
            uint32_t a_h[4][4], a_l[4][4];
            int arow = warp_m * 64 + (lane & 15);
            int acol = k0 + (lane >> 4) * 8;
            #pragma unroll
            for (int i = 0; i < 4; i++) {
                uint32_t ad = base + (((arow + i * 16) * PADK + acol) << 1);
                LDMX4(a_h[i][0], a_h[i][1], a_h[i][2], a_h[i][3], ad);
                LDMX4(a_l[i][0], a_l[i][1], a_l[i][2], a_l[i][3], ad + TILE_B);
            }
            // B fragments: 8x8 matrices with rows = n, cols = k (non-trans == col-major B frag)
            uint32_t b_h[4][2], b_l[4][2];
            int l8 = lane & 7, quad = lane >> 3;
            int brow_off = ((quad & 2) << 2) + l8;       // 0..7 or 8..15
            int bcol = k0 + ((quad & 1) << 3);
            #pragma unroll
            for (int j2 = 0; j2 < 2; j2++) {
                int brow = warp_n * 32 + j2 * 16 + brow_off;
                uint32_t bd = base + 2 * TILE_B + ((brow * PADK + bcol) << 1);
                uint32_t r0, r1, r2, r3;
                LDMX4(r0, r1, r2, r3, bd);
                b_h[2*j2][0] = r0; b_h[2*j2][1] = r1;
                b_h[2*j2+1][0] = r2; b_h[2*j2+1][1] = r3;
                LDMX4(r0, r1, r2, r3, bd + TILE_B);
                b_l[2*j2][0] = r0; b_l[2*j2][1] = r1;
                b_l[2*j2+1][0] = r2; b_l[2*j2+1][1] = r3;
            }
            #pragma unroll
            for (int i = 0; i < 4; i++)
                #pragma unroll
                for (int j = 0; j < 4; j++) {
                    MMA_BF16(acc[i][j], a_h[i], b_h[j]);
                    MMA_BF16(acc[i][j], a_h[i], b_l[j]);
                    MMA_BF16(acc[i][j], a_l[i], b_h[j]);
                }
        }
        __syncthreads();
    }

    // epilogue
    int g = lane >> 2, t = lane & 3;
    #pragma unroll
    for (int i = 0; i < 4; i++) {
        #pragma unroll
        for (int j = 0; j < 4; j++) {
            #pragma unroll
            for (int half = 0; half < 2; half++) {
                int m = bm + warp_m * 64 + i * 16 + g + half * 8;
                int n = bn + warp_n * 32 + j * 8 + 2 * t;
                float v0 = acc[i][j][2 * half]     + bias[n];
                float v1 = acc[i][j][2 * half + 1] + bias[n + 1];
                if (EPI == 0) {
                    size_t o = (size_t)m * DIM + n;
                    v0 += (n     < ACT) ? g_h[(size_t)m * ACT + n]     : g_xn[o];
                    v1 += (n + 1 < ACT) ? g_h[(size_t)m * ACT + n + 1] : g_xn[o + 1];
                    split_bf16(v0, g_yh[o], g_yl[o]);
                    split_bf16(v1, g_yh[o + 1], g_yl[o + 1]);
                } else if (EPI == 1) {
                    *(float2*)&Cf[(size_t)m * N + n] = make_float2(v0, v1);
                } else if (EPI == 2) {
                    v0 = 0.5f * v0 * (1.f + erff(v0 * 0.70710678118654752f));
                    v1 = 0.5f * v1 * (1.f + erff(v1 * 0.70710678118654752f));
                    size_t o = (size_t)m * HID + n;
                    split_bf16(v0, g_gh[o], g_gl[o]);
                    split_bf16(v1, g_gh[o + 1], g_gl[o + 1]);
                } else {
                    size_t o = (size_t)m * DIM + n;
                    v0 += __bfloat162float(g_y2h[o])     + __bfloat162float(g_y2l[o])     + addx[o];
                    v1 += __bfloat162float(g_y2h[o + 1]) + __bfloat162float(g_y2l[o + 1]) + addx[o + 1];
                    *(float2*)&Cf[o] = make_float2(v0, v1);
                }
            }
        }
    }
}

// ============ launch ============
extern "C" void kernel_launch(void* const* d_in, const int* in_sizes, int n_in,
                              void* d_out, int out_size) {
    const float* x      = (const float*)d_in[0];
    const float* norm_w = (const float*)d_in[1];
    const float* dw_w   = (const float*)d_in[2];
    const float* dw_b   = (const float*)d_in[3];
    const float* pw_w   = (const float*)d_in[4];
    const float* pw_b   = (const float*)d_in[5];
    const float* alpha  = (const float*)d_in[6];
    const float* beta   = (const float*)d_in[7];
    const float* W1_w   = (const float*)d_in[8];
    const float* W1_b   = (const float*)d_in[9];
    const float* W2_w   = (const float*)d_in[10];
    const float* W2_b   = (const float*)d_in[11];
    const float* down_w = (const float*)d_in[12];
    const float* down_b = (const float*)d_in[13];
    const float* up_w   = (const float*)d_in[14];
    const float* up_b   = (const float*)d_in[15];
    float* out = (float*)d_out;

    cudaFuncSetAttribute(hgemm<0>, cudaFuncAttributeMaxDynamicSharedMemorySize, SMEM_TOTAL);
    cudaFuncSetAttribute(hgemm<1>, cudaFuncAttributeMaxDynamicSharedMemorySize, SMEM_TOTAL);
    cudaFuncSetAttribute(hgemm<2>, cudaFuncAttributeMaxDynamicSharedMemorySize, SMEM_TOTAL);
    cudaFuncSetAttribute(hgemm<3>, cudaFuncAttributeMaxDynamicSharedMemorySize, SMEM_TOTAL);

    float *p_a, *p_b2;
    cudaGetSymbolAddress((void**)&p_a,  g_a);
    cudaGetSymbolAddress((void**)&p_b2, g_b2);
    __nv_bfloat16 *p_xch, *p_xcl, *p_yh, *p_yl, *p_y2h, *p_y2l, *p_gh, *p_gl;
    __nv_bfloat16 *p_pwh, *p_pwl, *p_w1h, *p_w1l, *p_w2h, *p_w2l, *p_dnh, *p_dnl, *p_uph, *p_upl;
    cudaGetSymbolAddress((void**)&p_xch, g_xch); cudaGetSymbolAddress((void**)&p_xcl, g_xcl);
    cudaGetSymbolAddress((void**)&p_yh,  g_yh);  cudaGetSymbolAddress((void**)&p_yl,  g_yl);
    cudaGetSymbolAddress((void**)&p_y2h, g_y2h); cudaGetSymbolAddress((void**)&p_y2l, g_y2l);
    cudaGetSymbolAddress((void**)&p_gh,  g_gh);  cudaGetSymbolAddress((void**)&p_gl,  g_gl);
    cudaGetSymbolAddress((void**)&p_pwh, g_pwh); cudaGetSymbolAddress((void**)&p_pwl, g_pwl);
    cudaGetSymbolAddress((void**)&p_w1h, g_w1h); cudaGetSymbolAddress((void**)&p_w1l, g_w1l);
    cudaGetSymbolAddress((void**)&p_w2h, g_w2h); cudaGetSymbolAddress((void**)&p_w2l, g_w2l);
    cudaGetSymbolAddress((void**)&p_dnh, g_dnh); cudaGetSymbolAddress((void**)&p_dnl, g_dnl);
    cudaGetSymbolAddress((void**)&p_uph, g_uph); cudaGetSymbolAddress((void**)&p_upl, g_upl);

    cvt_w_k<<<DIM*DIM/256, 256>>>(pw_w,   p_pwh, p_pwl, DIM*DIM);
    cvt_w_k<<<DIM*DIM/256, 256>>>(W1_w,   p_w1h, p_w1l, DIM*DIM);
    cvt_w_k<<<DIM*DIM/256, 256>>>(W2_w,   p_w2h, p_w2l, DIM*DIM);
    cvt_w_k<<<HID*DIM/256, 256>>>(down_w, p_dnh, p_dnl, HID*DIM);
    cvt_w_k<<<DIM*HID/256, 256>>>(up_w,   p_uph, p_upl, DIM*HID);

    rmsnorm_k<<<TOK, 256>>>(x, norm_w);
    conv_k<<<TOK * DIM / 256, 256>>>(dw_w, dw_b);
    rec1_k<<<BB * NCHUNK, ACT>>>(alpha, beta);
    rec2_k<<<BB, ACT>>>(alpha);
    rec3_k<<<BB * NCHUNK, ACT>>>(alpha);

    dim3 gBig(DIM / 128, TOK / 128);
    dim3 gDown(HID / 128, TOK / 128);

    hgemm<0><<<gBig, 256, SMEM_TOTAL>>>(p_xch, p_xcl, p_pwh, p_pwl, pw_b, nullptr, DIM, DIM, nullptr);
    hgemm<1><<<gBig, 256, SMEM_TOTAL>>>(p_yh, p_yl, p_w1h, p_w1l, W1_b, p_a,  DIM, DIM, nullptr);
    hgemm<1><<<gBig, 256, SMEM_TOTAL>>>(p_yh, p_yl, p_w2h, p_w2l, W2_b, p_b2, DIM, DIM, nullptr);
    gate_k<<<TOK * DIM / 256, 256>>>();
    hgemm<2><<<gDown, 256, SMEM_TOTAL>>>(p_y2h, p_y2l, p_dnh, p_dnl, down_b, nullptr, HID, DIM, nullptr);
    hgemm<3><<<gBig, 256, SMEM_TOTAL>>>(p_gh, p_gl, p_uph, p_upl, up_b, out, DIM, HID, x);
}

// round 4
// speedup vs baseline: 2.6226x; 1.1713x over previous
#include <cuda_runtime.h>
#include <cuda_fp16.h>
#include <math.h>
#include <stdint.h>

#define BB 8
#define LL 2048
#define DIM 1024
#define ACT 256
#define HID 256
#define TOK (BB*LL)
#define EPSV 1e-6f
#define KSZ 5
#define NCHUNK 32
#define CHLEN 64

// ============ scratch (no allocation allowed) ============
__device__ float g_xn[TOK*DIM];
__device__ float g_a [TOK*DIM];
__device__ float g_h [TOK*ACT];
__device__ float g_carry[BB*NCHUNK*ACT];
__device__ float g_F    [BB*NCHUNK*ACT];

__device__ __half g_xch[TOK*DIM], g_xcl[TOK*DIM];
__device__ __half g_yh [TOK*DIM], g_yl [TOK*DIM];
__device__ __half g_y2h[TOK*DIM], g_y2l[TOK*DIM];
__device__ __half g_gh [TOK*HID], g_gl [TOK*HID];
__device__ __half g_pw[DIM*DIM];
__device__ __half g_w1[DIM*DIM];
__device__ __half g_w2[DIM*DIM];
__device__ __half g_dn[HID*DIM];
__device__ __half g_up[DIM*HID];

__device__ __forceinline__ void split_fp16(float v, __half& h, __half& l) {
    h = __float2half_rn(v);
    l = __float2half_rn(v - __half2float(h));
}

__device__ __forceinline__ uint32_t smem_u32(const void* p) {
    uint32_t a;
    asm("{ .reg .u64 t; cvta.to.shared.u64 t, %1; cvt.u32.u64 %0, t; }" : "=r"(a) : "l"(p));
    return a;
}

#define CP_ASYNC16(sa, g) \
    asm volatile("cp.async.cg.shared.global [%0], [%1], 16;" :: "r"(sa), "l"(g))
#define CP_COMMIT() asm volatile("cp.async.commit_group;")
#define CP_WAIT(n)  asm volatile("cp.async.wait_group %0;" :: "n"(n))

#define LDMX4(r0, r1, r2, r3, addr) \
    asm volatile("ldmatrix.sync.aligned.m8n8.x4.shared.b16 {%0,%1,%2,%3}, [%4];" \
        : "=r"(r0), "=r"(r1), "=r"(r2), "=r"(r3) : "r"(addr))

#define MMA_F16(d, a, b) \
    asm volatile("mma.sync.aligned.m16n8k16.row.col.f32.f16.f16.f32 " \
        "{%0,%1,%2,%3}, {%4,%5,%6,%7}, {%8,%9}, {%0,%1,%2,%3};" \
        : "+f"((d)[0]), "+f"((d)[1]), "+f"((d)[2]), "+f"((d)[3]) \
        : "r"((a)[0]), "r"((a)[1]), "r"((a)[2]), "r"((a)[3]), "r"((b)[0]), "r"((b)[1]))

// ============ elementwise ============
__global__ void cvt_w_k(const float* __restrict__ src, __half* __restrict__ dst, int n) {
    int i = blockIdx.x * blockDim.x + threadIdx.x;
    if (i < n) dst[i] = __float2half_rn(src[i]);
}

__global__ void rmsnorm_k(const float* __restrict__ x, const float* __restrict__ w) {
    int tok = blockIdx.x;
    const float4* xr = (const float4*)(x + (size_t)tok * DIM);
    float4 v = xr[threadIdx.x];
    float ss = v.x*v.x + v.y*v.y + v.z*v.z + v.w*v.w;
    #pragma unroll
    for (int o = 16; o; o >>= 1) ss += __shfl_xor_sync(0xffffffffu, ss, o);
    __shared__ float red[8];
    if ((threadIdx.x & 31) == 0) red[threadIdx.x >> 5] = ss;
    __syncthreads();
    float tot = 0.f;
    #pragma unroll
    for (int i = 0; i < 8; i++) tot += red[i];
    float inv = rsqrtf(tot * (1.0f / DIM) + EPSV);
    float4 wv = ((const float4*)w)[threadIdx.x];
    float4 o;
    o.x = v.x * inv * wv.x; o.y = v.y * inv * wv.y;
    o.z = v.z * inv * wv.z; o.w = v.w * inv * wv.w;
    ((float4*)g_xn)[(size_t)tok * (DIM/4) + threadIdx.x] = o;
}

__global__ void conv_k(const float* __restrict__ dw_w, const float* __restrict__ dw_b) {
    int idx = blockIdx.x * blockDim.x + threadIdx.x;
    int c   = idx & (DIM - 1);
    int tok = idx >> 10;
    int t   = tok & (LL - 1);
    float acc = dw_b[c];
    #pragma unroll
    for (int k = 0; k < KSZ; k++) {
        int tt = t + k - 2;
        if (tt >= 0 && tt < LL)
            acc += g_xn[idx + (k - 2) * DIM] * dw_w[c * KSZ + k];
    }
    split_fp16(acc, g_xch[idx], g_xcl[idx]);
}

__global__ void rec1_k(const float* __restrict__ alpha, const float* __restrict__ beta) {
    int b = blockIdx.x / NCHUNK, j = blockIdx.x % NCHUNK;
    int c = threadIdx.x;
    float al = alpha[c], be = beta[c];
    float h = 0.f;
    int t0 = j * CHLEN;
    const float* src = g_xn + ((size_t)(b * LL + t0)) * DIM + c;
    float*       dst = g_h  + ((size_t)(b * LL + t0)) * ACT + c;
    #pragma unroll 8
    for (int i = 0; i < CHLEN; i++) {
        h = al * h + be * src[(size_t)i * DIM];
        dst[(size_t)i * ACT] = h;
    }
    g_carry[(b * NCHUNK + j) * ACT + c] = h;
}
__global__ void rec2_k(const float* __restrict__ alpha) {
    int b = blockIdx.x, c = threadIdx.x;
    float a64 = powf(alpha[c], (float)CHLEN);
    float F = 0.f;
    for (int j = 0; j < NCHUNK; j++) {
        int idx = (b * NCHUNK + j) * ACT + c;
        g_F[idx] = F;
        F = a64 * F + g_carry[idx];
    }
}
__global__ void rec3_k(const float* __restrict__ alpha) {
    int b = blockIdx.x / NCHUNK, j = blockIdx.x % NCHUNK;
    if (j == 0) return;
    int c = threadIdx.x;
    float inc = g_F[(b * NCHUNK + j) * ACT + c];
    float al = alpha[c];
    float m = inc * al;
    float* dst = g_h + ((size_t)(b * LL + j * CHLEN)) * ACT + c;
    #pragma unroll 8
    for (int i = 0; i < CHLEN; i++) {
        dst[(size_t)i * ACT] += m;
        m *= al;
    }
}

// ============ HMMA fp16 GEMM, 2-term split ============
// C[M,N] = (Ah+Al)[M,K] @ B[N,K]^T + bias + epilogue
// EPI 0: + concat(g_h | g_xn) -> g_yh/g_yl
// EPI 1: plain -> Cf (g_a)
// EPI 2: gelu  -> g_gh/g_gl
// EPI 3: + y2(recon) + addx -> Cf
// EPI 4: gate: y2 = (yh+yl) + sigmoid(g_a)*tanh(v) -> g_y2h/g_y2l
#define BLK_K 32
#define PADK 40                        // fp16 elems per smem row (32 + 8 pad)
#define TILE_B (128 * PADK * 2)        // 10240 bytes per tile
#define BUF_B  (3 * TILE_B)            // Ah, Al, Bh
#define NSTAGE 3
#define SMEM_TOTAL (NSTAGE * BUF_B)    // 92160

__device__ __forceinline__ void ld_tile(uint32_t dst, const __half* __restrict__ src,
                                        int ldK, int row0, int k0, int tid) {
    #pragma unroll
    for (int i = 0; i < 2; i++) {
        int c = tid + i * 256;
        int r = c >> 2, kc = (c & 3) * 8;
        const __half* g = src + (size_t)(row0 + r) * ldK + k0 + kc;
        CP_ASYNC16(dst + (r * PADK + kc) * 2, g);
    }
}

template<int EPI>
__global__ __launch_bounds__(256, 1) void hgemm(
    const __half* __restrict__ Ah, const __half* __restrict__ Al,
    const __half* __restrict__ Bh,
    const float* __restrict__ bias, float* __restrict__ Cf,
    int N, int K, const float* __restrict__ addx)
{
    extern __shared__ __align__(128) char smem[];
    uint32_t su = smem_u32(smem);
    int tid = threadIdx.x;
    int wid = tid >> 5, lane = tid & 31;
    int warp_m = wid & 1, warp_n = wid >> 1;     // 2 x 4 warps, warp tile 64x32
    int bm = blockIdx.y * 128, bn = blockIdx.x * 128;
    int NS = K / BLK_K;

    float acc[4][4][4];
    #pragma unroll
    for (int i = 0; i < 4; i++)
        #pragma unroll
        for (int j = 0; j < 4; j++)
            #pragma unroll
            for (int f = 0; f < 4; f++) acc[i][j][f] = 0.f;

    // prologue: prefetch 3 stages
    #pragma unroll
    for (int p = 0; p < NSTAGE; p++) {
        uint32_t b0 = su + p * BUF_B;
        int k0 = p * BLK_K;
        ld_tile(b0,              Ah, K, bm, k0, tid);
        ld_tile(b0 + TILE_B,     Al, K, bm, k0, tid);
        ld_tile(b0 + 2 * TILE_B, Bh, K, bn, k0, tid);
        CP_COMMIT();
    }

    for (int s = 0; s < NS; s++) {
        int rem = NS - 1 - s;
        if (rem >= 2) CP_WAIT(2); else if (rem == 1) CP_WAIT(1); else CP_WAIT(0);
        __syncthreads();

        uint32_t base = su + (s % NSTAGE) * BUF_B;
        #pragma unroll
        for (int kk = 0; kk < 2; kk++) {
            int k0 = kk * 16;
            uint32_t a_h[4][4], a_l[4][4];
            int arow = warp_m * 64 + (lane & 15);
            int acol = k0 + (lane >> 4) * 8;
            #pragma unroll
            for (int i = 0; i < 4; i++) {
                uint32_t ad = base + (((arow + i * 16) * PADK + acol) << 1);
                LDMX4(a_h[i][0], a_h[i][1], a_h[i][2], a_h[i][3], ad);
                LDMX4(a_l[i][0], a_l[i][1], a_l[i][2], a_l[i][3], ad + TILE_B);
            }
            uint32_t b_h[4][2];
            int l8 = lane & 7, quad = lane >> 3;
            int brow_off = ((quad & 2) << 2) + l8;
            int bcol = k0 + ((quad & 1) << 3);
            #pragma unroll
            for (int j2 = 0; j2 < 2; j2++) {
                int brow = warp_n * 32 + j2 * 16 + brow_off;
                uint32_t bd = base + 2 * TILE_B + ((brow * PADK + bcol) << 1);
                uint32_t r0, r1, r2, r3;
                LDMX4(r0, r1, r2, r3, bd);
                b_h[2*j2][0] = r0; b_h[2*j2][1] = r1;
                b_h[2*j2+1][0] = r2; b_h[2*j2+1][1] = r3;
            }
            #pragma unroll
            for (int i = 0; i < 4; i++)
                #pragma unroll
                for (int j = 0; j < 4; j++) {
                    MMA_F16(acc[i][j], a_h[i], b_h[j]);
                    MMA_F16(acc[i][j], a_l[i], b_h[j]);
                }
        }
        __syncthreads();
        if (s + NSTAGE < NS) {
            uint32_t nb = su + ((s + NSTAGE) % NSTAGE) * BUF_B;
            int k0 = (s + NSTAGE) * BLK_K;
            ld_tile(nb,              Ah, K, bm, k0, tid);
            ld_tile(nb + TILE_B,     Al, K, bm, k0, tid);
            ld_tile(nb + 2 * TILE_B, Bh, K, bn, k0, tid);
            CP_COMMIT();
        }
    }

    // epilogue
    int g = lane >> 2, t = lane & 3;
    #pragma unroll
    for (int i = 0; i < 4; i++) {
        #pragma unroll
        for (int j = 0; j < 4; j++) {
            #pragma unroll
            for (int half = 0; half < 2; half++) {
                int m = bm + warp_m * 64 + i * 16 + g + half * 8;
                int n = bn + warp_n * 32 + j * 8 + 2 * t;
                float v0 = acc[i][j][2 * half]     + bias[n];
                float v1 = acc[i][j][2 * half + 1] + bias[n + 1];
                if (EPI == 0) {
                    size_t o = (size_t)m * DIM + n;
                    v0 += (n     < ACT) ? g_h[(size_t)m * ACT + n]     : g_xn[o];
                    v1 += (n + 1 < ACT) ? g_h[(size_t)m * ACT + n + 1] : g_xn[o + 1];
                    split_fp16(v0, g_yh[o], g_yl[o]);
                    split_fp16(v1, g_yh[o + 1], g_yl[o + 1]);
                } else if (EPI == 1) {
                    *(float2*)&Cf[(size_t)m * N + n] = make_float2(v0, v1);
                } else if (EPI == 2) {
                    v0 = 0.5f * v0 * (1.f + erff(v0 * 0.70710678118654752f));
                    v1 = 0.5f * v1 * (1.f + erff(v1 * 0.70710678118654752f));
                    size_t o = (size_t)m * HID + n;
                    split_fp16(v0, g_gh[o], g_gl[o]);
                    split_fp16(v1, g_gh[o + 1], g_gl[o + 1]);
                } else if (EPI == 3) {
                    size_t o = (size_t)m * DIM + n;
                    v0 += __half2float(g_y2h[o])     + __half2float(g_y2l[o])     + addx[o];
                    v1 += __half2float(g_y2h[o + 1]) + __half2float(g_y2l[o + 1]) + addx[o + 1];
                    *(float2*)&Cf[o] = make_float2(v0, v1);
                } else {  // EPI 4: gate
                    size_t o = (size_t)m * DIM + n;
                    float y0 = __half2float(g_yh[o])     + __half2float(g_yl[o]);
                    float y1 = __half2float(g_yh[o + 1]) + __half2float(g_yl[o + 1]);
                    float a0 = g_a[o], a1 = g_a[o + 1];
                    float s0 = 1.f / (1.f + expf(-a0));
                    float s1 = 1.f / (1.f + expf(-a1));
                    float r0 = y0 + s0 * tanhf(v0);
                    float r1 = y1 + s1 * tanhf(v1);
                    split_fp16(r0, g_y2h[o], g_y2l[o]);
                    split_fp16(r1, g_y2h[o + 1], g_y2l[o + 1]);
                }
            }
        }
    }
}

// ============ launch ============
extern "C" void kernel_launch(void* const* d_in, const int* in_sizes, int n_in,
                              void* d_out, int out_size) {
    const float* x      = (const float*)d_in[0];
    const float* norm_w = (const float*)d_in[1];
    const float* dw_w   = (const float*)d_in[2];
    const float* dw_b   = (const float*)d_in[3];
    const float* pw_w   = (const float*)d_in[4];
    const float* pw_b   = (const float*)d_in[5];
    const float* alpha  = (const float*)d_in[6];
    const float* beta   = (const float*)d_in[7];
    const float* W1_w   = (const float*)d_in[8];
    const float* W1_b   = (const float*)d_in[9];
    const float* W2_w   = (const float*)d_in[10];
    const float* W2_b   = (const float*)d_in[11];
    const float* down_w = (const float*)d_in[12];
    const float* down_b = (const float*)d_in[13];
    const float* up_w   = (const float*)d_in[14];
    const float* up_b   = (const float*)d_in[15];
    float* out = (float*)d_out;

    cudaFuncSetAttribute(hgemm<0>, cudaFuncAttributeMaxDynamicSharedMemorySize, SMEM_TOTAL);
    cudaFuncSetAttribute(hgemm<1>, cudaFuncAttributeMaxDynamicSharedMemorySize, SMEM_TOTAL);
    cudaFuncSetAttribute(hgemm<2>, cudaFuncAttributeMaxDynamicSharedMemorySize, SMEM_TOTAL);
    cudaFuncSetAttribute(hgemm<3>, cudaFuncAttributeMaxDynamicSharedMemorySize, SMEM_TOTAL);
    cudaFuncSetAttribute(hgemm<4>, cudaFuncAttributeMaxDynamicSharedMemorySize, SMEM_TOTAL);

    float* p_a;
    cudaGetSymbolAddress((void**)&p_a, g_a);
    __half *p_xch, *p_xcl, *p_yh, *p_yl, *p_y2h, *p_y2l, *p_gh, *p_gl;
    __half *p_pw, *p_w1, *p_w2, *p_dn, *p_up;
    cudaGetSymbolAddress((void**)&p_xch, g_xch); cudaGetSymbolAddress((void**)&p_xcl, g_xcl);
    cudaGetSymbolAddress((void**)&p_yh,  g_yh);  cudaGetSymbolAddress((void**)&p_yl,  g_yl);
    cudaGetSymbolAddress((void**)&p_y2h, g_y2h); cudaGetSymbolAddress((void**)&p_y2l, g_y2l);
    cudaGetSymbolAddress((void**)&p_gh,  g_gh);  cudaGetSymbolAddress((void**)&p_gl,  g_gl);
    cudaGetSymbolAddress((void**)&p_pw,  g_pw);
    cudaGetSymbolAddress((void**)&p_w1,  g_w1);
    cudaGetSymbolAddress((void**)&p_w2,  g_w2);
    cudaGetSymbolAddress((void**)&p_dn,  g_dn);
    cudaGetSymbolAddress((void**)&p_up,  g_up);

    cvt_w_k<<<DIM*DIM/256, 256>>>(pw_w,   p_pw, DIM*DIM);
    cvt_w_k<<<DIM*DIM/256, 256>>>(W1_w,   p_w1, DIM*DIM);
    cvt_w_k<<<DIM*DIM/256, 256>>>(W2_w,   p_w2, DIM*DIM);
    cvt_w_k<<<HID*DIM/256, 256>>>(down_w, p_dn, HID*DIM);
    cvt_w_k<<<DIM*HID/256, 256>>>(up_w,   p_up, DIM*HID);

    rmsnorm_k<<<TOK, 256>>>(x, norm_w);
    conv_k<<<TOK * DIM / 256, 256>>>(dw_w, dw_b);
    rec1_k<<<BB * NCHUNK, ACT>>>(alpha, beta);
    rec2_k<<<BB, ACT>>>(alpha);
    rec3_k<<<BB * NCHUNK, ACT>>>(alpha);

    dim3 gBig(DIM / 128, TOK / 128);
    dim3 gDown(HID / 128, TOK / 128);

    // y = xc @ pw^T + pw_b + concat(h | xn)
    hgemm<0><<<gBig, 256, SMEM_TOTAL>>>(p_xch, p_xcl, p_pw, pw_b, nullptr, DIM, DIM, nullptr);
    // a = y @ W1^T + b1
    hgemm<1><<<gBig, 256, SMEM_TOTAL>>>(p_yh, p_yl, p_w1, W1_b, p_a, DIM, DIM, nullptr);
    // b2 = y @ W2^T + b2 ; fused gate -> y2
    hgemm<4><<<gBig, 256, SMEM_TOTAL>>>(p_yh, p_yl, p_w2, W2_b, nullptr, DIM, DIM, nullptr);
    // g = gelu(y2 @ down^T + down_b)
    hgemm<2><<<gDown, 256, SMEM_TOTAL>>>(p_y2h, p_y2l, p_dn, down_b, nullptr, HID, DIM, nullptr);
    // out = g @ up^T + up_b + y2 + x
    hgemm<3><<<gBig, 256, SMEM_TOTAL>>>(p_gh, p_gl, p_up, up_b, out, DIM, HID, x);
}

// round 5
// speedup vs baseline: 4.8783x; 1.8601x over previous
#include <cuda_runtime.h>
#include <cuda_fp16.h>
#include <math.h>
#include <stdint.h>

#define BB 8
#define LL 2048
#define DIM 1024
#define ACT 256
#define HID 256
#define TOK (BB*LL)
#define EPSV 1e-6f
#define KSZ 5
#define NCHUNK 32
#define CHLEN 64

// ============ scratch (no allocation allowed) ============
__device__ float g_xn [TOK*DIM];   // rmsnorm out (fp32, additive path + rec input)
__device__ float g_a  [TOK*DIM];   // W1 gemm out (fp32)
__device__ float g_yf [TOK*DIM];   // y  (fp32, additive path)
__device__ float g_y2f[TOK*DIM];   // y2 (fp32, additive path)
__device__ float g_h  [TOK*ACT];
__device__ float g_carry[BB*NCHUNK*ACT];
__device__ float g_F    [BB*NCHUNK*ACT];

__device__ __half g_xch[TOK*DIM];  // conv out  (gemm A)
__device__ __half g_yh [TOK*DIM];  // y fp16    (gemm A)
__device__ __half g_y2h[TOK*DIM];  // y2 fp16   (gemm A)
__device__ __half g_gh [TOK*HID];  // gelu fp16 (gemm A)
__device__ __half g_pw[DIM*DIM];
__device__ __half g_w1[DIM*DIM];
__device__ __half g_w2[DIM*DIM];
__device__ __half g_dn[HID*DIM];
__device__ __half g_up[DIM*HID];

__device__ __forceinline__ uint32_t smem_u32(const void* p) {
    uint32_t a;
    asm("{ .reg .u64 t; cvta.to.shared.u64 t, %1; cvt.u32.u64 %0, t; }" : "=r"(a) : "l"(p));
    return a;
}

#define CP_ASYNC16(sa, g) \
    asm volatile("cp.async.cg.shared.global [%0], [%1], 16;" :: "r"(sa), "l"(g))
#define CP_COMMIT() asm volatile("cp.async.commit_group;")
#define CP_WAIT(n)  asm volatile("cp.async.wait_group %0;" :: "n"(n))

#define LDMX4(r0, r1, r2, r3, addr) \
    asm volatile("ldmatrix.sync.aligned.m8n8.x4.shared.b16 {%0,%1,%2,%3}, [%4];" \
        : "=r"(r0), "=r"(r1), "=r"(r2), "=r"(r3) : "r"(addr))

#define MMA_F16(d, a, b) \
    asm volatile("mma.sync.aligned.m16n8k16.row.col.f32.f16.f16.f32 " \
        "{%0,%1,%2,%3}, {%4,%5,%6,%7}, {%8,%9}, {%0,%1,%2,%3};" \
        : "+f"((d)[0]), "+f"((d)[1]), "+f"((d)[2]), "+f"((d)[3]) \
        : "r"((a)[0]), "r"((a)[1]), "r"((a)[2]), "r"((a)[3]), "r"((b)[0]), "r"((b)[1]))

// ============ elementwise ============
__global__ void cvt_w_k(const float* __restrict__ src, __half* __restrict__ dst, int n) {
    int i = blockIdx.x * blockDim.x + threadIdx.x;
    if (i < n) dst[i] = __float2half_rn(src[i]);
}

__global__ void rmsnorm_k(const float* __restrict__ x, const float* __restrict__ w) {
    int tok = blockIdx.x;
    const float4* xr = (const float4*)(x + (size_t)tok * DIM);
    float4 v = xr[threadIdx.x];
    float ss = v.x*v.x + v.y*v.y + v.z*v.z + v.w*v.w;
    #pragma unroll
    for (int o = 16; o; o >>= 1) ss += __shfl_xor_sync(0xffffffffu, ss, o);
    __shared__ float red[8];
    if ((threadIdx.x & 31) == 0) red[threadIdx.x >> 5] = ss;
    __syncthreads();
    float tot = 0.f;
    #pragma unroll
    for (int i = 0; i < 8; i++) tot += red[i];
    float inv = rsqrtf(tot * (1.0f / DIM) + EPSV);
    float4 wv = ((const float4*)w)[threadIdx.x];
    float4 o;
    o.x = v.x * inv * wv.x; o.y = v.y * inv * wv.y;
    o.z = v.z * inv * wv.z; o.w = v.w * inv * wv.w;
    ((float4*)g_xn)[(size_t)tok * (DIM/4) + threadIdx.x] = o;
}

__global__ void conv_k(const float* __restrict__ dw_w, const float* __restrict__ dw_b) {
    int idx = blockIdx.x * blockDim.x + threadIdx.x;
    int c   = idx & (DIM - 1);
    int tok = idx >> 10;
    int t   = tok & (LL - 1);
    float acc = dw_b[c];
    #pragma unroll
    for (int k = 0; k < KSZ; k++) {
        int tt = t + k - 2;
        if (tt >= 0 && tt < LL)
            acc += g_xn[idx + (k - 2) * DIM] * dw_w[c * KSZ + k];
    }
    g_xch[idx] = __float2half_rn(acc);
}

__global__ void rec1_k(const float* __restrict__ alpha, const float* __restrict__ beta) {
    int b = blockIdx.x / NCHUNK, j = blockIdx.x % NCHUNK;
    int c = threadIdx.x;
    float al = alpha[c], be = beta[c];
    float h = 0.f;
    int t0 = j * CHLEN;
    const float* src = g_xn + ((size_t)(b * LL + t0)) * DIM + c;
    float*       dst = g_h  + ((size_t)(b * LL + t0)) * ACT + c;
    #pragma unroll 8
    for (int i = 0; i < CHLEN; i++) {
        h = al * h + be * src[(size_t)i * DIM];
        dst[(size_t)i * ACT] = h;
    }
    g_carry[(b * NCHUNK + j) * ACT + c] = h;
}
__global__ void rec2_k(const float* __restrict__ alpha) {
    int b = blockIdx.x, c = threadIdx.x;
    float a64 = powf(alpha[c], (float)CHLEN);
    float F = 0.f;
    for (int j = 0; j < NCHUNK; j++) {
        int idx = (b * NCHUNK + j) * ACT + c;
        g_F[idx] = F;
        F = a64 * F + g_carry[idx];
    }
}
__global__ void rec3_k(const float* __restrict__ alpha) {
    int b = blockIdx.x / NCHUNK, j = blockIdx.x % NCHUNK;
    if (j == 0) return;
    int c = threadIdx.x;
    float inc = g_F[(b * NCHUNK + j) * ACT + c];
    float al = alpha[c];
    float m = inc * al;
    float* dst = g_h + ((size_t)(b * LL + j * CHLEN)) * ACT + c;
    #pragma unroll 8
    for (int i = 0; i < CHLEN; i++) {
        dst[(size_t)i * ACT] += m;
        m *= al;
    }
}

// ============ HMMA fp16 GEMM (single term) ============
// C[M,N] = A[M,K] @ B[N,K]^T + bias + epilogue
// EPI 0: + concat(g_h | g_xn) -> g_yf (fp32) + g_yh (fp16)
// EPI 1: plain -> Cf (g_a)
// EPI 2: gelu  -> g_gh
// EPI 3: + g_y2f + addx -> Cf (out)
// EPI 4: gate: y2 = g_yf + sigmoid(g_a)*tanh(v) -> g_y2f + g_y2h
#define BLK_K 32
#define PADK 40                        // fp16 elems per smem row (32 + 8 pad)
#define TILE_B (128 * PADK * 2)        // 10240 bytes per tile
#define BUF_B  (2 * TILE_B)            // A, B
#define NSTAGE 3
#define SMEM_TOTAL (NSTAGE * BUF_B)    // 61440

__device__ __forceinline__ void ld_tile(uint32_t dst, const __half* __restrict__ src,
                                        int ldK, int row0, int k0, int tid) {
    #pragma unroll
    for (int i = 0; i < 2; i++) {
        int c = tid + i * 256;
        int r = c >> 2, kc = (c & 3) * 8;
        const __half* g = src + (size_t)(row0 + r) * ldK + k0 + kc;
        CP_ASYNC16(dst + (r * PADK + kc) * 2, g);
    }
}

template<int EPI>
__global__ __launch_bounds__(256, 2) void hgemm(
    const __half* __restrict__ Ah, const __half* __restrict__ Bh,
    const float* __restrict__ bias, float* __restrict__ Cf,
    int N, int K, const float* __restrict__ addx)
{
    extern __shared__ __align__(128) char smem[];
    uint32_t su = smem_u32(smem);
    int tid = threadIdx.x;
    int wid = tid >> 5, lane = tid & 31;
    int warp_m = wid & 3, warp_n = wid >> 2;     // 4 x 2 warps, warp tile 32x64
    int bm = blockIdx.y * 128, bn = blockIdx.x * 128;
    int NS = K / BLK_K;

    float acc[2][8][4];
    #pragma unroll
    for (int i = 0; i < 2; i++)
        #pragma unroll
        for (int j = 0; j < 8; j++)
            #pragma unroll
            for (int f = 0; f < 4; f++) acc[i][j][f] = 0.f;

    #pragma unroll
    for (int p = 0; p < NSTAGE; p++) {
        uint32_t b0 = su + p * BUF_B;
        int k0 = p * BLK_K;
        ld_tile(b0,          Ah, K, bm, k0, tid);
        ld_tile(b0 + TILE_B, Bh, K, bn, k0, tid);
        CP_COMMIT();
    }

    for (int s = 0; s < NS; s++) {
        int rem = NS - 1 - s;
        if (rem >= 2) CP_WAIT(2); else if (rem == 1) CP_WAIT(1); else CP_WAIT(0);
        __syncthreads();

        uint32_t base = su + (s % NSTAGE) * BUF_B;
        #pragma unroll
        for (int kk = 0; kk < 2; kk++) {
            int k0 = kk * 16;
            // A: 32 rows -> 2 m16 frags
            uint32_t a_h[2][4];
            int arow = warp_m * 32 + (lane & 15);
            int acol = k0 + (lane >> 4) * 8;
            #pragma unroll
            for (int i = 0; i < 2; i++) {
                uint32_t ad = base + (((arow + i * 16) * PADK + acol) << 1);
                LDMX4(a_h[i][0], a_h[i][1], a_h[i][2], a_h[i][3], ad);
            }
            // B: 64 rows -> 8 n8 frags via 4 x LDMX4
            uint32_t b_h[8][2];
            int l8 = lane & 7, quad = lane >> 3;
            int brow_off = ((quad & 2) << 2) + l8;
            int bcol = k0 + ((quad & 1) << 3);
            #pragma unroll
            for (int j2 = 0; j2 < 4; j2++) {
                int brow = warp_n * 64 + j2 * 16 + brow_off;
                uint32_t bd = base + TILE_B + ((brow * PADK + bcol) << 1);
                uint32_t r0, r1, r2, r3;
                LDMX4(r0, r1, r2, r3, bd);
                b_h[2*j2][0] = r0;   b_h[2*j2][1] = r1;
                b_h[2*j2+1][0] = r2; b_h[2*j2+1][1] = r3;
            }
            #pragma unroll
            for (int i = 0; i < 2; i++)
                #pragma unroll
                for (int j = 0; j < 8; j++)
                    MMA_F16(acc[i][j], a_h[i], b_h[j]);
        }
        __syncthreads();
        if (s + NSTAGE < NS) {
            uint32_t nb = su + ((s + NSTAGE) % NSTAGE) * BUF_B;
            int k0 = (s + NSTAGE) * BLK_K;
            ld_tile(nb,          Ah, K, bm, k0, tid);
            ld_tile(nb + TILE_B, Bh, K, bn, k0, tid);
            CP_COMMIT();
        }
    }

    // epilogue
    int g = lane >> 2, t = lane & 3;
    #pragma unroll
    for (int i = 0; i < 2; i++) {
        #pragma unroll
        for (int j = 0; j < 8; j++) {
            #pragma unroll
            for (int half = 0; half < 2; half++) {
                int m = bm + warp_m * 32 + i * 16 + g + half * 8;
                int n = bn + warp_n * 64 + j * 8 + 2 * t;
                float v0 = acc[i][j][2 * half]     + bias[n];
                float v1 = acc[i][j][2 * half + 1] + bias[n + 1];
                if (EPI == 0) {
                    size_t o = (size_t)m * DIM + n;
                    v0 += (n     < ACT) ? g_h[(size_t)m * ACT + n]     : g_xn[o];
                    v1 += (n + 1 < ACT) ? g_h[(size_t)m * ACT + n + 1] : g_xn[o + 1];
                    *(float2*)&g_yf[o] = make_float2(v0, v1);
                    *(__half2*)&g_yh[o] = __floats2half2_rn(v0, v1);
                } else if (EPI == 1) {
                    *(float2*)&Cf[(size_t)m * N + n] = make_float2(v0, v1);
                } else if (EPI == 2) {
                    v0 = 0.5f * v0 * (1.f + erff(v0 * 0.70710678118654752f));
                    v1 = 0.5f * v1 * (1.f + erff(v1 * 0.70710678118654752f));
                    size_t o = (size_t)m * HID + n;
                    *(__half2*)&g_gh[o] = __floats2half2_rn(v0, v1);
                } else if (EPI == 3) {
                    size_t o = (size_t)m * DIM + n;
                    v0 += g_y2f[o]     + addx[o];
                    v1 += g_y2f[o + 1] + addx[o + 1];
                    *(float2*)&Cf[o] = make_float2(v0, v1);
                } else {  // EPI 4: gate
                    size_t o = (size_t)m * DIM + n;
                    float y0 = g_yf[o], y1 = g_yf[o + 1];
                    float a0 = g_a[o],  a1 = g_a[o + 1];
                    float s0 = 1.f / (1.f + expf(-a0));
                    float s1 = 1.f / (1.f + expf(-a1));
                    float r0 = y0 + s0 * tanhf(v0);
                    float r1 = y1 + s1 * tanhf(v1);
                    *(float2*)&g_y2f[o] = make_float2(r0, r1);
                    *(__half2*)&g_y2h[o] = __floats2half2_rn(r0, r1);
                }
            }
        }
    }
}

// ============ launch ============
extern "C" void kernel_launch(void* const* d_in, const int* in_sizes, int n_in,
                              void* d_out, int out_size) {
    const float* x      = (const float*)d_in[0];
    const float* norm_w = (const float*)d_in[1];
    const float* dw_w   = (const float*)d_in[2];
    const float* dw_b   = (const float*)d_in[3];
    const float* pw_w   = (const float*)d_in[4];
    const float* pw_b   = (const float*)d_in[5];
    const float* alpha  = (const float*)d_in[6];
    const float* beta   = (const float*)d_in[7];
    const float* W1_w   = (const float*)d_in[8];
    const float* W1_b   = (const float*)d_in[9];
    const float* W2_w   = (const float*)d_in[10];
    const float* W2_b   = (const float*)d_in[11];
    const float* down_w = (const float*)d_in[12];
    const float* down_b = (const float*)d_in[13];
    const float* up_w   = (const float*)d_in[14];
    const float* up_b   = (const float*)d_in[15];
    float* out = (float*)d_out;

    cudaFuncSetAttribute(hgemm<0>, cudaFuncAttributeMaxDynamicSharedMemorySize, SMEM_TOTAL);
    cudaFuncSetAttribute(hgemm<1>, cudaFuncAttributeMaxDynamicSharedMemorySize, SMEM_TOTAL);
    cudaFuncSetAttribute(hgemm<2>, cudaFuncAttributeMaxDynamicSharedMemorySize, SMEM_TOTAL);
    cudaFuncSetAttribute(hgemm<3>, cudaFuncAttributeMaxDynamicSharedMemorySize, SMEM_TOTAL);
    cudaFuncSetAttribute(hgemm<4>, cudaFuncAttributeMaxDynamicSharedMemorySize, SMEM_TOTAL);

    float* p_a;
    cudaGetSymbolAddress((void**)&p_a, g_a);
    __half *p_xch, *p_yh, *p_y2h, *p_gh, *p_pw, *p_w1, *p_w2, *p_dn, *p_up;
    cudaGetSymbolAddress((void**)&p_xch, g_xch);
    cudaGetSymbolAddress((void**)&p_yh,  g_yh);
    cudaGetSymbolAddress((void**)&p_y2h, g_y2h);
    cudaGetSymbolAddress((void**)&p_gh,  g_gh);
    cudaGetSymbolAddress((void**)&p_pw,  g_pw);
    cudaGetSymbolAddress((void**)&p_w1,  g_w1);
    cudaGetSymbolAddress((void**)&p_w2,  g_w2);
    cudaGetSymbolAddress((void**)&p_dn,  g_dn);
    cudaGetSymbolAddress((void**)&p_up,  g_up);

    cvt_w_k<<<DIM*DIM/256, 256>>>(pw_w,   p_pw, DIM*DIM);
    cvt_w_k<<<DIM*DIM/256, 256>>>(W1_w,   p_w1, DIM*DIM);
    cvt_w_k<<<DIM*DIM/256, 256>>>(W2_w,   p_w2, DIM*DIM);
    cvt_w_k<<<HID*DIM/256, 256>>>(down_w, p_dn, HID*DIM);
    cvt_w_k<<<DIM*HID/256, 256>>>(up_w,   p_up, DIM*HID);

    rmsnorm_k<<<TOK, 256>>>(x, norm_w);
    conv_k<<<TOK * DIM / 256, 256>>>(dw_w, dw_b);
    rec1_k<<<BB * NCHUNK, ACT>>>(alpha, beta);
    rec2_k<<<BB, ACT>>>(alpha);
    rec3_k<<<BB * NCHUNK, ACT>>>(alpha);

    dim3 gBig(DIM / 128, TOK / 128);
    dim3 gDown(HID / 128, TOK / 128);

    // y = xc @ pw^T + pw_b + concat(h | xn)
    hgemm<0><<<gBig, 256, SMEM_TOTAL>>>(p_xch, p_pw, pw_b, nullptr, DIM, DIM, nullptr);
    // a = y @ W1^T + b1
    hgemm<1><<<gBig, 256, SMEM_TOTAL>>>(p_yh, p_w1, W1_b, p_a, DIM, DIM, nullptr);
    // b2 = y @ W2^T + b2 ; fused gate -> y2
    hgemm<4><<<gBig, 256, SMEM_TOTAL>>>(p_yh, p_w2, W2_b, nullptr, DIM, DIM, nullptr);
    // g = gelu(y2 @ down^T + down_b)
    hgemm<2><<<gDown, 256, SMEM_TOTAL>>>(p_y2h, p_dn, down_b, nullptr, HID, DIM, nullptr);
    // out = g @ up^T + up_b + y2 + x
    hgemm<3><<<gBig, 256, SMEM_TOTAL>>>(p_gh, p_up, up_b, out, DIM, HID, x);
}